// round 14
// baseline (speedup 1.0000x reference)
#include <cuda_runtime.h>
#include <cuda_fp16.h>
#include <cstdint>

// KANLinear as one fused fp16 mma.sync GEMM.
// GEMM: BK=64, 3-stage cp.async pipeline, 8 warps (2x4, 64x64 tiles), 128x256 CTA
// (best measured config, R6). Prep: single merged kernel (W-fragments + bias).
// K = 4096 (constant basis j=0 folded into bias).

#define IN_F   512
#define OUT_F  512
#define NROWS  8192
#define KTOT   4096
#define BM     128
#define BN     256
#define BK     64
#define NCHUNK (KTOT / BK)     // 64
#define NSTAGE 3

// g_W fragment order: [c 64][nb2 32][ks 4][lane 32][8 halves]  (nb2 = o>>4)
__device__ __half g_W[(size_t)NCHUNK * 32 * 4 * 32 * 8];   // 4 MB
__device__ float  g_bias[OUT_F];

// -------- helpers --------
__device__ __forceinline__ uint32_t smem_u32(const void* p) {
    uint32_t a;
    asm("{ .reg .u64 t; cvta.to.shared.u64 t, %1; cvt.u32.u64 %0, t; }" : "=r"(a) : "l"(p));
    return a;
}
#define CP_ASYNC16(dst, src) \
    asm volatile("cp.async.cg.shared.global [%0], [%1], 16;" :: "r"(dst), "l"(src))
#define CP_COMMIT()  asm volatile("cp.async.commit_group;" ::: "memory")
#define CP_WAIT(n)   asm volatile("cp.async.wait_group %0;" :: "n"(n) : "memory")

__device__ __forceinline__ void mma_fp16(float* d, uint32_t a0, uint32_t a1,
                                         uint32_t a2, uint32_t a3,
                                         uint32_t b0, uint32_t b1) {
    asm volatile(
        "mma.sync.aligned.m16n8k16.row.col.f32.f16.f16.f32 "
        "{%0,%1,%2,%3}, {%4,%5,%6,%7}, {%8,%9}, {%0,%1,%2,%3};"
        : "+f"(d[0]), "+f"(d[1]), "+f"(d[2]), "+f"(d[3])
        : "r"(a0), "r"(a1), "r"(a2), "r"(a3), "r"(b0), "r"(b1));
}

// -------- merged prep: W blocks [0,2048) + bias blocks [2048,2560), 128 thr --------
// W block (c, nb2): writes one contiguous 1KB region [ks 4][lane 32][16B].
__global__ void __launch_bounds__(128) prep_kernel(
    const float* __restrict__ coeff,
    const float* __restrict__ scale_base,
    const float* __restrict__ scale_spline,
    const float* __restrict__ base_bias)
{
    const int bid = blockIdx.x;
    const int tid = threadIdx.x;

    if (bid < 2048) {
        // ---- W expansion (R11 layout, measured correct) ----
        __shared__ float scf[16][64];   // [o_local][i_local*8 + j]
        __shared__ float ssm[16][8];
        __shared__ float sbm[16][8];
        const int c = bid >> 5, nb2 = bid & 31;
        const int o0 = nb2 * 16, i0 = c * 8;

        {
            const int oi = tid >> 3, part = tid & 7;
            const float* src = coeff + ((size_t)(o0 + oi) * IN_F + i0) * 8 + part * 8;
            *(float4*)&scf[oi][part * 8]     = *(const float4*)src;
            *(float4*)&scf[oi][part * 8 + 4] = *(const float4*)(src + 4);
            ssm[oi][part] = scale_spline[(o0 + oi) * IN_F + i0 + part];
            sbm[oi][part] = scale_base[(o0 + oi) * IN_F + i0 + part];
        }
        __syncthreads();

        const int ks = tid >> 5, lane = tid & 31;
        const int g = lane >> 2, t = lane & 3;
        __half2 h[4];
#pragma unroll
        for (int nbl = 0; nbl < 2; nbl++) {
#pragma unroll
            for (int rb = 0; rb < 2; rb++) {
                const int o_loc = nbl * 8 + g;
                const int i_loc = ks * 2 + rb;
                const float ss = ssm[o_loc][i_loc];
                const float* cf = &scf[o_loc][i_loc * 8];
                float w0 = ss * cf[2 * t + 1];
                float w1 = (t < 3) ? ss * cf[2 * t + 2] : sbm[o_loc][i_loc];
                h[nbl * 2 + rb] = __floats2half2_rn(w0, w1);
            }
        }
        ((uint4*)g_W)[((size_t)c * 32 + nb2) * 128 + ks * 32 + lane] =
            *(const uint4*)h;
    } else {
        // ---- bias: rowsum(base_bias) + folded j=0 spline term ----
        __shared__ float red[128];
        const int o = bid - 2048;
        float s = 0.f;
#pragma unroll
        for (int q = 0; q < 4; q++) {
            const int i = tid + q * 128;
            s += base_bias[o * IN_F + i]
               + scale_spline[o * IN_F + i] * coeff[((size_t)o * IN_F + i) * 8];
        }
        red[tid] = s;
        __syncthreads();
        for (int off = 64; off > 0; off >>= 1) {
            if (tid < off) red[tid] += red[tid + off];
            __syncthreads();
        }
        if (tid == 0) g_bias[o] = red[0];
    }
}

// -------- GEMM (R6 config) --------
// A buffer: [mt 8][ks 4] rows of 33*16B = 528B (16B pad kills STS conflicts)
// B buffer: [nb2 16][ks 4][lane 32][16B] = 32KB
#define A_ROWB   528
#define A_BUFB   (8 * 4 * A_ROWB)      // 16896
#define B_BUFB   32768
#define SM_A(s)  ((uint32_t)(s) * A_BUFB)
#define SM_B(s)  ((uint32_t)(NSTAGE * A_BUFB + (s) * B_BUFB))
#define SM_TOTAL (NSTAGE * (A_BUFB + B_BUFB))   // 148992

__device__ __forceinline__ void gen_a(char* Abuf, float4 xv, int ar, int ah) {
    const int m = ar & 15, mt = ar >> 4, g = m & 7, hi = m >> 3;
    const int rot = m >> 1;
    float xs[4] = {xv.x, xv.y, xv.z, xv.w};
#pragma unroll
    for (int fl = 0; fl < 4; fl++) {
        float xc = fminf(fmaxf(xs[fl], -1.f), 1.f);
        float vals[8];
        float b = xc;
        vals[0] = b;
#pragma unroll
        for (int tt = 1; tt < 7; tt++) { b = 2.f * xc * b - 1.f; vals[tt] = b; }
        vals[7] = xc / (1.f + __expf(-xc));   // silu
        const int fi  = ah * 4 + fl;          // feature in chunk (0..7)
        const int ks  = fi >> 1;
        const int reg = (fi & 1) * 2 + hi;
        char* base = Abuf + (mt * 4 + ks) * A_ROWB + reg * 4;
#pragma unroll
        for (int t0 = 0; t0 < 4; t0++) {
            int tp = (t0 + rot) & 3;
            *(__half2*)(base + (g * 4 + tp) * 16) =
                __floats2half2_rn(vals[2 * tp], vals[2 * tp + 1]);
        }
    }
}

__device__ __forceinline__ void cp_b(int c, uint32_t dst, int tid, int col0) {
    const __half* src = g_W + ((size_t)c * 32 + (col0 >> 4)) * 1024 + tid * 8;
    uint32_t d = dst + (uint32_t)tid * 16;
#pragma unroll
    for (int q = 0; q < 8; q++)
        CP_ASYNC16(d + q * 4096u, src + q * 2048);
}

__device__ __forceinline__ void do_mma(const char* Asm, const char* Bsm,
                                       float acc[4][8][4], int wm, int wn, int lane) {
#pragma unroll
    for (int ks = 0; ks < 4; ks++) {
        uint4 a[4];
#pragma unroll
        for (int i = 0; i < 4; i++)
            a[i] = *(const uint4*)(Asm + ((wm * 4 + i) * 4 + ks) * A_ROWB + lane * 16);
#pragma unroll
        for (int j2 = 0; j2 < 4; j2++) {
            uint4 bb = *(const uint4*)(Bsm + (((wn * 4 + j2) * 4 + ks) * 32 + lane) * 16);
#pragma unroll
            for (int i = 0; i < 4; i++) {
                mma_fp16(acc[i][j2 * 2 + 0], a[i].x, a[i].y, a[i].z, a[i].w, bb.x, bb.y);
                mma_fp16(acc[i][j2 * 2 + 1], a[i].x, a[i].y, a[i].z, a[i].w, bb.z, bb.w);
            }
        }
    }
}

__global__ void __launch_bounds__(256, 1) kan_mma_kernel(
    const float* __restrict__ x, float* __restrict__ out)
{
    extern __shared__ char smem[];
    const uint32_t sb = smem_u32(smem);

    const int tid = threadIdx.x;
    const int wid = tid >> 5, lane = tid & 31;
    const int wm = wid & 1, wn = wid >> 1;       // 2 x 4 warp grid, 64x64 tiles
    const int row0 = blockIdx.x * BM;
    const int col0 = blockIdx.y * BN;

    const int ar = tid >> 1, ah = tid & 1;
    const float* xrow = x + (size_t)(row0 + ar) * IN_F + ah * 4;

    float acc[4][8][4];
#pragma unroll
    for (int i = 0; i < 4; i++)
#pragma unroll
        for (int j = 0; j < 8; j++)
#pragma unroll
            for (int q = 0; q < 4; q++) acc[i][j][q] = 0.f;

    // prologue: chunks 0 and 1 in flight
    cp_b(0, sb + SM_B(0), tid, col0); CP_COMMIT();
    cp_b(1, sb + SM_B(1), tid, col0); CP_COMMIT();
    gen_a(smem + SM_A(0), *(const float4*)xrow,       ar, ah);
    gen_a(smem + SM_A(1), *(const float4*)(xrow + 8), ar, ah);
    CP_WAIT(1);
    __syncthreads();

    for (int c = 0; c < NCHUNK; c++) {
        const int cur = c % NSTAGE;
        const bool has = (c + 2 < NCHUNK);
        const int nxt = (c + 2) % NSTAGE;
        float4 xn;
        if (has) {
            xn = *(const float4*)(xrow + (c + 2) * 8);   // early LDG
            cp_b(c + 2, sb + SM_B(nxt), tid, col0);
            CP_COMMIT();
        }
        do_mma(smem + SM_A(cur), smem + SM_B(cur), acc, wm, wn, lane);
        if (has) {
            gen_a(smem + SM_A(nxt), xn, ar, ah);
            CP_WAIT(1);
        } else {
            CP_WAIT(0);
        }
        __syncthreads();
    }

    // epilogue: add bias, float2 stores
    const int g = lane >> 2, t2 = (lane & 3) * 2;
#pragma unroll
    for (int j = 0; j < 8; j++) {
        const int col = col0 + wn * 64 + j * 8 + t2;
        const float2 bs = *(const float2*)&g_bias[col];
#pragma unroll
        for (int i = 0; i < 4; i++) {
            const int r = row0 + wm * 64 + i * 16 + g;
            float2 v0 = make_float2(acc[i][j][0] + bs.x, acc[i][j][1] + bs.y);
            float2 v1 = make_float2(acc[i][j][2] + bs.x, acc[i][j][3] + bs.y);
            *(float2*)(out + (size_t)r * OUT_F + col)       = v0;
            *(float2*)(out + (size_t)(r + 8) * OUT_F + col) = v1;
        }
    }
}

extern "C" void kernel_launch(void* const* d_in, const int* in_sizes, int n_in,
                              void* d_out, int out_size) {
    const float* x            = (const float*)d_in[0];
    const float* coeff        = (const float*)d_in[1];
    const float* scale_base   = (const float*)d_in[2];
    const float* scale_spline = (const float*)d_in[3];
    const float* base_bias    = (const float*)d_in[4];
    float* out = (float*)d_out;
    (void)in_sizes; (void)n_in; (void)out_size;

    static bool attr_set = false;
    if (!attr_set) {
        cudaFuncSetAttribute(kan_mma_kernel,
                             cudaFuncAttributeMaxDynamicSharedMemorySize, SM_TOTAL);
        attr_set = true;
    }

    prep_kernel<<<2048 + OUT_F, 128>>>(coeff, scale_base, scale_spline, base_bias);

    dim3 grid(NROWS / BM, OUT_F / BN);   // 64 x 2 = 128 CTAs
    kan_mma_kernel<<<grid, 256, SM_TOTAL>>>(x, out);
}

// round 15
// speedup vs baseline: 1.5816x; 1.5816x over previous
#include <cuda_runtime.h>
#include <cuda_fp16.h>
#include <cstdint>

// KANLinear as one fused fp16 mma.sync GEMM (best-verified R8 configuration).
// BK=128, 2-stage cp.async pipeline, 8 warps (2x4, 64x64 tiles), 128x256 CTA.
// K = 4096 (constant basis j=0 folded into bias). Single fused prep kernel.

#define IN_F   512
#define OUT_F  512
#define NROWS  8192
#define KTOT   4096
#define BM     128
#define BN     256
#define BK     128
#define NCHUNK (KTOT / BK)     // 32
#define NSTAGE 2

// g_W in mma-B fragment order, 2 n8-groups packed per 16B for LDS.128:
//   [c 32][nb2 32][ks 8][lane 32][8 halves]   (nb2 = o>>4)
__device__ __half g_W[(size_t)NCHUNK * 32 * 8 * 32 * 8];   // 4 MB
__device__ float  g_bias[OUT_F];

// -------- helpers --------
__device__ __forceinline__ uint32_t smem_u32(const void* p) {
    uint32_t a;
    asm("{ .reg .u64 t; cvta.to.shared.u64 t, %1; cvt.u32.u64 %0, t; }" : "=r"(a) : "l"(p));
    return a;
}
#define CP_ASYNC16(dst, src) \
    asm volatile("cp.async.cg.shared.global [%0], [%1], 16;" :: "r"(dst), "l"(src))
#define CP_COMMIT()  asm volatile("cp.async.commit_group;" ::: "memory")
#define CP_WAIT(n)   asm volatile("cp.async.wait_group %0;" :: "n"(n) : "memory")

__device__ __forceinline__ void mma_fp16(float* d, uint32_t a0, uint32_t a1,
                                         uint32_t a2, uint32_t a3,
                                         uint32_t b0, uint32_t b1) {
    asm volatile(
        "mma.sync.aligned.m16n8k16.row.col.f32.f16.f16.f32 "
        "{%0,%1,%2,%3}, {%4,%5,%6,%7}, {%8,%9}, {%0,%1,%2,%3};"
        : "+f"(d[0]), "+f"(d[1]), "+f"(d[2]), "+f"(d[3])
        : "r"(a0), "r"(a1), "r"(a2), "r"(a3), "r"(b0), "r"(b1));
}

// -------- fused prep: weight expansion + bias, one block per output o --------
__global__ void __launch_bounds__(512) prep_kernel(
    const float* __restrict__ coeff,
    const float* __restrict__ scale_base,
    const float* __restrict__ scale_spline,
    const float* __restrict__ base_bias)
{
    __shared__ float red[16];
    const int o = blockIdx.x;
    const int i = threadIdx.x;

    const float4 c0 = *(const float4*)(coeff + ((size_t)o * IN_F + i) * 8);
    const float4 c1 = *(const float4*)(coeff + ((size_t)o * IN_F + i) * 8 + 4);
    const float ss = scale_spline[o * IN_F + i];
    const float sb = scale_base[o * IN_F + i];
    const float bb = base_bias[o * IN_F + i];

    float w[8];
    w[0] = ss * c0.y; w[1] = ss * c0.z; w[2] = ss * c0.w;
    w[3] = ss * c1.x; w[4] = ss * c1.y; w[5] = ss * c1.z; w[6] = ss * c1.w;
    w[7] = sb;

    const int c  = i >> 4;
    const int ks = (i & 15) >> 1;
    const int rb = i & 1;
    const int nb = o >> 3, g = o & 7, nb2 = nb >> 1;
    const size_t flatbase = (((size_t)c * 32 + nb2) * 8 + ks) * 32;
#pragma unroll
    for (int t = 0; t < 4; t++) {
        const int lane = g * 4 + t;
        ((__half2*)g_W)[(flatbase + lane) * 4 + (nb & 1) * 2 + rb] =
            __floats2half2_rn(w[2 * t], w[2 * t + 1]);
    }

    // bias: rowsum(base_bias) + folded j=0 spline term (warp-shuffle reduce)
    float s = bb + ss * c0.x;
#pragma unroll
    for (int off = 16; off > 0; off >>= 1)
        s += __shfl_xor_sync(0xFFFFFFFFu, s, off);
    if ((i & 31) == 0) red[i >> 5] = s;
    __syncthreads();
    if (i < 16) {
        float v = red[i];
#pragma unroll
        for (int off = 8; off > 0; off >>= 1)
            v += __shfl_xor_sync(0xFFFFu, v, off);
        if (i == 0) g_bias[o] = v;
    }
}

// -------- GEMM --------
// A buffer: [mt 8][ks 8] rows of 33*16B = 528B (16B pad kills STS conflicts)
//   within row: [lane 32][a0 a1 a2 a3 as half2]
// B buffer: [nb2 16][ks 8][lane 32][16B] = 64KB
#define A_ROWB   528
#define A_BUFB   (8 * 8 * A_ROWB)      // 33792
#define B_BUFB   65536
#define SM_A(s)  ((uint32_t)(s) * A_BUFB)
#define SM_B(s)  ((uint32_t)(2 * A_BUFB + (s) * B_BUFB))
#define SM_TOTAL (2 * (A_BUFB + B_BUFB))   // 198656

__device__ __forceinline__ void gen_a(char* Abuf, float4 xa, float4 xb,
                                      int ar, int ah) {
    const int m = ar & 15, mt = ar >> 4, g = m & 7, hi = m >> 3;
    const int rot = m >> 1;
    float xs[8] = {xa.x, xa.y, xa.z, xa.w, xb.x, xb.y, xb.z, xb.w};
#pragma unroll
    for (int fl = 0; fl < 8; fl++) {
        float xc = fminf(fmaxf(xs[fl], -1.f), 1.f);
        float vals[8];
        float b = xc;
        vals[0] = b;
#pragma unroll
        for (int t = 1; t < 7; t++) { b = 2.f * xc * b - 1.f; vals[t] = b; }
        vals[7] = xc / (1.f + __expf(-xc));   // silu
        const int fi  = ah * 8 + fl;          // feature in chunk (0..15)
        const int ks  = fi >> 1;
        const int reg = (fi & 1) * 2 + hi;
        char* base = Abuf + (mt * 8 + ks) * A_ROWB + reg * 4;
#pragma unroll
        for (int t0 = 0; t0 < 4; t0++) {
            int tp = (t0 + rot) & 3;
            *(__half2*)(base + (g * 4 + tp) * 16) =
                __floats2half2_rn(vals[2 * tp], vals[2 * tp + 1]);
        }
    }
}

__device__ __forceinline__ void cp_b(int c, uint32_t dst, int tid, int col0) {
    const __half* src = g_W + ((size_t)c * 32 + (col0 >> 4)) * 2048 + tid * 8;
    uint32_t d = dst + (uint32_t)tid * 16;
#pragma unroll
    for (int q = 0; q < 16; q++)
        CP_ASYNC16(d + q * 4096u, src + q * 2048);
}

__device__ __forceinline__ void do_mma(const char* Asm, const char* Bsm,
                                       float acc[4][8][4], int wm, int wn, int lane) {
#pragma unroll
    for (int ks = 0; ks < 8; ks++) {
        uint4 a[4];
#pragma unroll
        for (int i = 0; i < 4; i++)
            a[i] = *(const uint4*)(Asm + ((wm * 4 + i) * 8 + ks) * A_ROWB + lane * 16);
#pragma unroll
        for (int j2 = 0; j2 < 4; j2++) {
            uint4 bb = *(const uint4*)(Bsm + (((wn * 4 + j2) * 8 + ks) * 32 + lane) * 16);
#pragma unroll
            for (int i = 0; i < 4; i++) {
                mma_fp16(acc[i][j2 * 2 + 0], a[i].x, a[i].y, a[i].z, a[i].w, bb.x, bb.y);
                mma_fp16(acc[i][j2 * 2 + 1], a[i].x, a[i].y, a[i].z, a[i].w, bb.z, bb.w);
            }
        }
    }
}

__global__ void __launch_bounds__(256, 1) kan_mma_kernel(
    const float* __restrict__ x, float* __restrict__ out)
{
    extern __shared__ char smem[];
    const uint32_t sb = smem_u32(smem);

    const int tid = threadIdx.x;
    const int wid = tid >> 5, lane = tid & 31;
    const int wm = wid & 1, wn = wid >> 1;       // 2 x 4 warp grid, 64x64 tiles
    const int row0 = blockIdx.x * BM;
    const int col0 = blockIdx.y * BN;

    const int ar = tid >> 1, ah = tid & 1;
    const float* xrow = x + (size_t)(row0 + ar) * IN_F + ah * 8;

    float acc[4][8][4];
#pragma unroll
    for (int i = 0; i < 4; i++)
#pragma unroll
        for (int j = 0; j < 8; j++)
#pragma unroll
            for (int q = 0; q < 4; q++) acc[i][j][q] = 0.f;

    // prologue: chunk 0
    cp_b(0, sb + SM_B(0), tid, col0); CP_COMMIT();
    gen_a(smem + SM_A(0), *(const float4*)xrow, *(const float4*)(xrow + 4), ar, ah);
    CP_WAIT(0);
    __syncthreads();

    for (int c = 0; c < NCHUNK; c++) {
        const int cur = c & 1;
        const bool has = (c + 1 < NCHUNK);
        const int nxt = cur ^ 1;
        float4 xa, xb;
        if (has) {
            xa = *(const float4*)(xrow + (c + 1) * 16);       // early LDG
            xb = *(const float4*)(xrow + (c + 1) * 16 + 4);
            cp_b(c + 1, sb + SM_B(nxt), tid, col0);
            CP_COMMIT();
        }
        do_mma(smem + SM_A(cur), smem + SM_B(cur), acc, wm, wn, lane);
        if (has) {
            gen_a(smem + SM_A(nxt), xa, xb, ar, ah);
            CP_WAIT(0);   // cp for c+1 hidden behind full chunk of MMA
        }
        __syncthreads();
    }

    // epilogue: add bias, float2 stores
    const int g = lane >> 2, t2 = (lane & 3) * 2;
#pragma unroll
    for (int j = 0; j < 8; j++) {
        const int col = col0 + wn * 64 + j * 8 + t2;
        const float2 bs = *(const float2*)&g_bias[col];
#pragma unroll
        for (int i = 0; i < 4; i++) {
            const int r = row0 + wm * 64 + i * 16 + g;
            float2 v0 = make_float2(acc[i][j][0] + bs.x, acc[i][j][1] + bs.y);
            float2 v1 = make_float2(acc[i][j][2] + bs.x, acc[i][j][3] + bs.y);
            *(float2*)(out + (size_t)r * OUT_F + col)       = v0;
            *(float2*)(out + (size_t)(r + 8) * OUT_F + col) = v1;
        }
    }
}

extern "C" void kernel_launch(void* const* d_in, const int* in_sizes, int n_in,
                              void* d_out, int out_size) {
    const float* x            = (const float*)d_in[0];
    const float* coeff        = (const float*)d_in[1];
    const float* scale_base   = (const float*)d_in[2];
    const float* scale_spline = (const float*)d_in[3];
    const float* base_bias    = (const float*)d_in[4];
    float* out = (float*)d_out;
    (void)in_sizes; (void)n_in; (void)out_size;

    static bool attr_set = false;
    if (!attr_set) {
        cudaFuncSetAttribute(kan_mma_kernel,
                             cudaFuncAttributeMaxDynamicSharedMemorySize, SM_TOTAL);
        attr_set = true;
    }

    prep_kernel<<<OUT_F, 512>>>(coeff, scale_base, scale_spline, base_bias);

    dim3 grid(NROWS / BM, OUT_F / BN);   // 64 x 2 = 128 CTAs
    kan_mma_kernel<<<grid, 256, SM_TOTAL>>>(x, out);
}